// round 10
// baseline (speedup 1.0000x reference)
#include <cuda_runtime.h>
#include <cuda.h>
#include <cuda_bf16.h>
#include <cstdint>

// ============================================================================
// Problem constants (fixed by setup_inputs: B=8192, D=1024, T=20, S=256)
// ============================================================================
#define D_DIM   1024
#define MAX_B   8192
#define MAX_TS  5120

#define M_TILE  64                // 2 CTAs/SM; N stays task-local
#define N_TILE  256               // == BUFFER_SIZE -> segmented min is CTA-local
#define K_TILE  128               // int8: 128 elems = 128B = one SW128 atom row
#define NK      (D_DIM / K_TILE)  // 8 K-stages per tile
#define STAGES  2
#define NWC     4                 // 4 warps: 1(M) x 4(N), warp tile 64x64
#define THREADS (NWC * 32)        // 128

#define A_STAGE_BYTES (M_TILE * 128)                    // 8192
#define B_STAGE_BYTES (N_TILE * 128)                    // 32768
#define STAGE_BYTES   (A_STAGE_BYTES + B_STAGE_BYTES)   // 40960

#define SMEM_FULL   0                      // 2 x 8B mbarriers
#define SMEM_EMPTY  16                     // 2 x 8B mbarriers
#define SMEM_EPI    64                     // 2 buffers x 256 floats = 2048
#define SMEM_A      4096                   // 1024-aligned
#define SMEM_B      (SMEM_A + STAGES * A_STAGE_BYTES)   // 20480
#define SMEM_TOTAL  (SMEM_B + STAGES * B_STAGE_BYTES)   // 86016 (x2 CTAs = 168KB)

// ============================================================================
// Scratch (module-load allocation, legal under _HX_ENFORCE)
// ============================================================================
__device__ __align__(1024) int8_t g_Xq[MAX_B * D_DIM];
__device__ __align__(1024) int8_t g_Wq[MAX_TS * D_DIM];
__device__ float g_sX[MAX_B];
__device__ float g_sW[MAX_TS];

// ============================================================================
// PTX helpers (base sm_80/sm_90 ISA only — target is sm_100 base, no tcgen05)
// ============================================================================
__device__ __forceinline__ uint32_t smem_u32(const void* p) {
    uint32_t a;
    asm("{ .reg .u64 t; cvta.to.shared.u64 t, %1; cvt.u32.u64 %0, t; }"
        : "=r"(a) : "l"(p));
    return a;
}

#define MBARRIER_INIT(mbar, cnt) \
    asm volatile("mbarrier.init.shared.b64 [%0], %1;" \
                 :: "r"((uint32_t)(mbar)), "r"((uint32_t)(cnt)) : "memory")
#define MBARRIER_EXPECT_TX(mbar, bytes) \
    asm volatile("mbarrier.arrive.expect_tx.shared.b64 _, [%0], %1;" \
                 :: "r"((uint32_t)(mbar)), "r"((uint32_t)(bytes)) : "memory")
#define MBARRIER_ARRIVE(mbar) \
    asm volatile("mbarrier.arrive.shared.b64 _, [%0];" \
                 :: "r"((uint32_t)(mbar)) : "memory")

#define MBARRIER_WAIT_PARITY(mbar, parity) do {                                  \
    uint32_t _m = (uint32_t)(mbar);                                              \
    uint32_t _p = (uint32_t)(parity);                                            \
    uint32_t _done;                                                              \
    asm volatile("{\n\t.reg .pred p;\n\t"                                        \
        "mbarrier.try_wait.parity.acquire.cta.shared::cta.b64 p, [%1], %2;\n\t"  \
        "selp.b32 %0, 1, 0, p;\n\t}"                                             \
        : "=r"(_done) : "r"(_m), "r"(_p) : "memory");                            \
    if (!_done) {                                                                \
        asm volatile("{\n\t.reg .pred P1;\n\t"                                   \
            "WAIT_LOOP_%=:\n\t"                                                  \
            "mbarrier.try_wait.parity.acquire.cta.shared::cta.b64 P1, [%0], %1, 0x989680;\n\t" \
            "@P1 bra.uni WAIT_DONE_%=;\n\t"                                      \
            "bra.uni WAIT_LOOP_%=;\n\t"                                          \
            "WAIT_DONE_%=:\n\t}"                                                 \
            :: "r"(_m), "r"(_p) : "memory");                                     \
    }                                                                            \
} while (0)

#define TMA_LOAD_2D(smem_addr, tmap, cx, cy, mbar) \
    asm volatile("cp.async.bulk.tensor.2d.shared::cluster.global.tile.mbarrier::complete_tx::bytes " \
                 "[%0], [%1, {%2, %3}], [%4];" \
                 :: "r"((uint32_t)(smem_addr)), "l"(tmap), \
                    "r"((int)(cx)), "r"((int)(cy)), "r"((uint32_t)(mbar)) : "memory")

#define LDSM_X4(r0, r1, r2, r3, addr) \
    asm volatile("ldmatrix.sync.aligned.m8n8.x4.shared.b16 {%0,%1,%2,%3}, [%4];" \
                 : "=r"(r0), "=r"(r1), "=r"(r2), "=r"(r3) : "r"(addr))

// int8 IMMA: byte-identical fragment layout to HMMA m16n8k16 with f16 -> 2 x s8
#define IMMA16832(c, a, b) \
    asm volatile("mma.sync.aligned.m16n8k32.row.col.s32.s8.s8.s32 " \
                 "{%0,%1,%2,%3}, {%4,%5,%6,%7}, {%8,%9}, {%0,%1,%2,%3};" \
                 : "+r"((c)[0]), "+r"((c)[1]), "+r"((c)[2]), "+r"((c)[3]) \
                 : "r"((a)[0]), "r"((a)[1]), "r"((a)[2]), "r"((a)[3]), \
                   "r"((b)[0]), "r"((b)[1]))

#define SWZ128(x) ((x) ^ (((x) >> 3) & 0x70))

// ============================================================================
// Kernel 1: fused L2-normalize + per-row symmetric int8 quantize.
// ============================================================================
__global__ void __launch_bounds__(256) normquant_kernel(
    const float* __restrict__ x, const float* __restrict__ w,
    int8_t* __restrict__ xq, int8_t* __restrict__ wq,
    float* __restrict__ sx, float* __restrict__ sw, int B) {
    int blk = blockIdx.x;
    const float* in; int8_t* outq; float* outs; int row;
    if (blk < B) { in = x; outq = xq; outs = sx; row = blk; }
    else         { in = w; outq = wq; outs = sw; row = blk - B; }

    const float4 v = reinterpret_cast<const float4*>(in)[(size_t)row * 256 + threadIdx.x];
    float ss = v.x * v.x + v.y * v.y + v.z * v.z + v.w * v.w;
    float ma = fmaxf(fmaxf(fabsf(v.x), fabsf(v.y)), fmaxf(fabsf(v.z), fabsf(v.w)));
#pragma unroll
    for (int o = 16; o > 0; o >>= 1) {
        ss += __shfl_xor_sync(0xFFFFFFFFu, ss, o);
        ma = fmaxf(ma, __shfl_xor_sync(0xFFFFFFFFu, ma, o));
    }
    __shared__ float wss[8], wma[8];
    if ((threadIdx.x & 31) == 0) { wss[threadIdx.x >> 5] = ss; wma[threadIdx.x >> 5] = ma; }
    __syncthreads();
    float tot = wss[0] + wss[1] + wss[2] + wss[3] + wss[4] + wss[5] + wss[6] + wss[7];
    float mx  = fmaxf(fmaxf(fmaxf(wma[0], wma[1]), fmaxf(wma[2], wma[3])),
                      fmaxf(fmaxf(wma[4], wma[5]), fmaxf(wma[6], wma[7])));
    float rq = 127.0f / mx;
    int q0 = __float2int_rn(v.x * rq), q1 = __float2int_rn(v.y * rq);
    int q2 = __float2int_rn(v.z * rq), q3 = __float2int_rn(v.w * rq);
    uint32_t pk = (uint32_t)(q0 & 0xFF) | ((uint32_t)(q1 & 0xFF) << 8) |
                  ((uint32_t)(q2 & 0xFF) << 16) | ((uint32_t)(q3 & 0xFF) << 24);
    reinterpret_cast<uint32_t*>(outq)[(size_t)row * 256 + threadIdx.x] = pk;
    if (threadIdx.x == 0) outs[row] = mx * rsqrtf(tot) / 127.0f;
}

// ============================================================================
// Kernel 2: PERSISTENT IMMA GEMM, 2 CTAs/SM. 128 threads (4 warps 1Mx4N,
// 64x64 warp tile). Co-resident CTA fills each other's barrier bubbles.
// Lagged refill (stage g-1 reloaded at top of iter g) + double-buffered epi.
// ============================================================================
__global__ void __launch_bounds__(THREADS, 2) gemm_segmax_kernel(
    const __grid_constant__ CUtensorMap tma_a,
    const __grid_constant__ CUtensorMap tma_b,
    const float* __restrict__ sA, const float* __restrict__ sB,
    float* __restrict__ out, int num_tasks, int n_mtiles, int total_tiles) {
    extern __shared__ char smem[];
    uint32_t sb = smem_u32(smem);
    int tid = threadIdx.x;
    int wid = tid >> 5;
    int l   = tid & 31;
    int warp_n = wid;        // 0..3 -> cols warp_n*64 (all warps share M rows)

    int ntile_cta = 0;
    for (int t = blockIdx.x; t < total_tiles; t += gridDim.x) ntile_cta++;
    if (ntile_cta == 0) return;
    int total_stg = ntile_cta * NK;

    if (tid == 0) {
#pragma unroll
        for (int s = 0; s < STAGES; s++) {
            MBARRIER_INIT(sb + SMEM_FULL  + s * 8, 1);
            MBARRIER_INIT(sb + SMEM_EMPTY + s * 8, NWC);
        }
    }
    __syncthreads();

    // ---- Prologue: fill both stages ----
    if (tid == 0) {
        int m0p = (blockIdx.x % n_mtiles) * M_TILE;
        int n0p = (blockIdx.x / n_mtiles) * N_TILE;
#pragma unroll
        for (int gg = 0; gg < STAGES; gg++) {
            uint32_t fb = sb + SMEM_FULL + gg * 8;
            MBARRIER_EXPECT_TX(fb, STAGE_BYTES);
            TMA_LOAD_2D(sb + SMEM_A + gg * A_STAGE_BYTES, &tma_a, gg * K_TILE, m0p, fb);
            TMA_LOAD_2D(sb + SMEM_B + gg * B_STAGE_BYTES, &tma_b, gg * K_TILE, n0p, fb);
        }
    }

    // Lane-invariant byte offsets within a stage tile (row stride 128B)
    uint32_t aoff[4];
#pragma unroll
    for (int mt = 0; mt < 4; mt++)
        aoff[mt] = (uint32_t)(mt * 16 + (l & 15)) * 128 + ((l >> 4) & 1) * 16;
    uint32_t boff[4];
#pragma unroll
    for (int jp = 0; jp < 4; jp++)
        boff[jp] = (uint32_t)(warp_n * 64 + jp * 16 + ((l & 16) >> 1) + (l & 7)) * 128
                 + ((l & 8) ? 16u : 0u);

    int g = 0;                               // global stage counter
    int ebuf = 0;                            // epilogue buffer selector
    for (int t = blockIdx.x; t < total_tiles; t += gridDim.x) {
        int m0 = (t % n_mtiles) * M_TILE;
        int n0 = (t / n_mtiles) * N_TILE;

        int c[4][8][4];
#pragma unroll
        for (int mt = 0; mt < 4; mt++)
#pragma unroll
            for (int j = 0; j < 8; j++)
#pragma unroll
                for (int i = 0; i < 4; i++) c[mt][j][i] = 0;

#pragma unroll 1
        for (int kt = 0; kt < NK; kt++, g++) {
            int s = g & (STAGES - 1);
            int ph = (g / STAGES) & 1;
            uint32_t fb = sb + SMEM_FULL  + s * 8;
            uint32_t eb = sb + SMEM_EMPTY + s * 8;

            // ---- lagged refill: stage consumed LAST iteration (g-1) ----
            if (tid == 0 && g > 0) {
                int gp = g - 1;
                int gr = gp + STAGES;
                if (gr < total_stg) {
                    int sp  = gp & (STAGES - 1);
                    int php = (gp / STAGES) & 1;
                    uint32_t ebp = sb + SMEM_EMPTY + sp * 8;
                    uint32_t fbp = sb + SMEM_FULL  + sp * 8;
                    MBARRIER_WAIT_PARITY(ebp, php);
                    int tt = gr / NK, ktt = gr % NK;
                    int tgl = blockIdx.x + tt * gridDim.x;
                    MBARRIER_EXPECT_TX(fbp, STAGE_BYTES);
                    TMA_LOAD_2D(sb + SMEM_A + sp * A_STAGE_BYTES, &tma_a,
                                ktt * K_TILE, (tgl % n_mtiles) * M_TILE, fbp);
                    TMA_LOAD_2D(sb + SMEM_B + sp * B_STAGE_BYTES, &tma_b,
                                ktt * K_TILE, (tgl / n_mtiles) * N_TILE, fbp);
                }
            }

            MBARRIER_WAIT_PARITY(fb, ph);

            uint32_t a_sb = sb + SMEM_A + s * A_STAGE_BYTES;
            uint32_t b_sb = sb + SMEM_B + s * B_STAGE_BYTES;

#pragma unroll
            for (int ks = 0; ks < 4; ks++) {          // 4 x k32 per 128B stage
                uint32_t a[4][4];
#pragma unroll
                for (int mt = 0; mt < 4; mt++) {
                    uint32_t off = aoff[mt] + ks * 32;
                    LDSM_X4(a[mt][0], a[mt][1], a[mt][2], a[mt][3], a_sb + SWZ128(off));
                }
                uint32_t b[8][2];
#pragma unroll
                for (int jp = 0; jp < 4; jp++) {
                    uint32_t off = boff[jp] + ks * 32;
                    LDSM_X4(b[2 * jp][0], b[2 * jp][1], b[2 * jp + 1][0], b[2 * jp + 1][1],
                            b_sb + SWZ128(off));
                }
#pragma unroll
                for (int mt = 0; mt < 4; mt++)
#pragma unroll
                    for (int j = 0; j < 8; j++)
                        IMMA16832(c[mt][j], a[mt], b[j]);
            }
            if (l == 0) MBARRIER_ARRIVE(eb);          // warp done with stage s
        }

        // ---- Epilogue: sB[col] scale, segmented max, sA[row] scale ----
        float* epi = reinterpret_cast<float*>(smem + SMEM_EPI) + ebuf * 256;
        int col0 = warp_n * 64 + 2 * (l & 3);
#pragma unroll
        for (int mt = 0; mt < 4; mt++) {
            float mlo = -1e30f, mhi = -1e30f;
#pragma unroll
            for (int j = 0; j < 8; j++) {
                float s0 = __ldg(&sB[n0 + col0 + j * 8]);
                float s1 = __ldg(&sB[n0 + col0 + j * 8 + 1]);
                mlo = fmaxf(mlo, fmaxf((float)c[mt][j][0] * s0, (float)c[mt][j][1] * s1));
                mhi = fmaxf(mhi, fmaxf((float)c[mt][j][2] * s0, (float)c[mt][j][3] * s1));
            }
            mlo = fmaxf(mlo, __shfl_xor_sync(0xFFFFFFFFu, mlo, 1));
            mlo = fmaxf(mlo, __shfl_xor_sync(0xFFFFFFFFu, mlo, 2));
            mhi = fmaxf(mhi, __shfl_xor_sync(0xFFFFFFFFu, mhi, 1));
            mhi = fmaxf(mhi, __shfl_xor_sync(0xFFFFFFFFu, mhi, 2));
            if ((l & 3) == 0) {
                int rlo = mt * 16 + (l >> 2);
                epi[warp_n * 64 + rlo]     = mlo;
                epi[warp_n * 64 + rlo + 8] = mhi;
            }
        }
        __syncthreads();    // single barrier per tile (epi is double-buffered)

        if (tid < 64) {
            float v = fmaxf(fmaxf(epi[tid], epi[64 + tid]),
                            fmaxf(epi[128 + tid], epi[192 + tid]));
            float dot = v * __ldg(&sA[m0 + tid]);
            float sq = fmaxf(2.0f - 2.0f * dot, 1e-12f);
            out[(size_t)(m0 + tid) * num_tasks + (t / n_mtiles)] = -sqrtf(sq);
        }
        ebuf ^= 1;
    }
}

// ============================================================================
// Host side
// ============================================================================
typedef CUresult (*EncodeFn)(CUtensorMap*, CUtensorMapDataType, cuuint32_t, void*,
                             const cuuint64_t*, const cuuint64_t*, const cuuint32_t*,
                             const cuuint32_t*, CUtensorMapInterleave, CUtensorMapSwizzle,
                             CUtensorMapL2promotion, CUtensorMapFloatOOBfill);

static void encode_2d(EncodeFn enc, CUtensorMap* tm, void* ptr,
                      uint64_t rows, uint32_t box_rows) {
    cuuint64_t dims[2]    = {D_DIM, rows};
    cuuint64_t strides[1] = {D_DIM};              // int8: 1024 bytes per row
    cuuint32_t box[2]     = {K_TILE, box_rows};   // 128 int8 = 128B = SW128 span
    cuuint32_t es[2]      = {1, 1};
    enc(tm, CU_TENSOR_MAP_DATA_TYPE_UINT8, 2, ptr, dims, strides, box, es,
        CU_TENSOR_MAP_INTERLEAVE_NONE, CU_TENSOR_MAP_SWIZZLE_128B,
        CU_TENSOR_MAP_L2_PROMOTION_L2_128B, CU_TENSOR_MAP_FLOAT_OOB_FILL_NONE);
}

extern "C" void kernel_launch(void* const* d_in, const int* in_sizes, int n_in,
                              void* d_out, int out_size) {
    const float* x = (const float*)d_in[0];
    const float* w = (const float*)d_in[1];
    const int B  = in_sizes[0] / D_DIM;   // 8192
    const int TS = in_sizes[1] / D_DIM;   // 5120
    const int T  = TS / 256;              // 20
    float* out = (float*)d_out;

    int8_t *dXq = nullptr, *dWq = nullptr;
    float *dsX = nullptr, *dsW = nullptr;
    cudaGetSymbolAddress((void**)&dXq, g_Xq);
    cudaGetSymbolAddress((void**)&dWq, g_Wq);
    cudaGetSymbolAddress((void**)&dsX, g_sX);
    cudaGetSymbolAddress((void**)&dsW, g_sW);

    normquant_kernel<<<B + TS, 256>>>(x, w, dXq, dWq, dsX, dsW, B);

    void* fn = nullptr;
    cudaDriverEntryPointQueryResult qr;
    cudaGetDriverEntryPoint("cuTensorMapEncodeTiled", &fn, cudaEnableDefault, &qr);
    EncodeFn enc = (EncodeFn)fn;

    CUtensorMap tma_a, tma_b;
    encode_2d(enc, &tma_a, dXq, (uint64_t)B,  M_TILE);
    encode_2d(enc, &tma_b, dWq, (uint64_t)TS, N_TILE);

    int nsm = 148;
    cudaDeviceGetAttribute(&nsm, cudaDevAttrMultiProcessorCount, 0);

    int n_mtiles = B / M_TILE;            // 128
    int total_tiles = n_mtiles * T;       // 2560

    cudaFuncSetAttribute(gemm_segmax_kernel,
                         cudaFuncAttributeMaxDynamicSharedMemorySize, SMEM_TOTAL);
    gemm_segmax_kernel<<<2 * nsm, THREADS, SMEM_TOTAL>>>(
        tma_a, tma_b, dsX, dsW, out, T, n_mtiles, total_tiles);
}

// round 11
// speedup vs baseline: 1.0552x; 1.0552x over previous
#include <cuda_runtime.h>
#include <cuda.h>
#include <cuda_bf16.h>
#include <cstdint>

// ============================================================================
// Problem constants (fixed by setup_inputs: B=8192, D=1024, T=20, S=256)
// ============================================================================
#define D_DIM   1024
#define MAX_B   8192
#define MAX_TS  5120

#define M_TILE  128
#define N_TILE  256               // == BUFFER_SIZE -> segmented min is CTA-local
#define K_TILE  128               // int8: 128 elems = 128B = one SW128 atom row
#define NK      (D_DIM / K_TILE)  // 8 K-stages per tile
#define STAGES  4
#define NWC     8                 // 8 warps: 2(M) x 4(N), warp tile 64x64
#define THREADS (NWC * 32)        // 256

#define A_STAGE_BYTES (M_TILE * 128)                    // 16384
#define B_STAGE_BYTES (N_TILE * 128)                    // 32768
#define STAGE_BYTES   (A_STAGE_BYTES + B_STAGE_BYTES)   // 49152

#define SMEM_FULL   0                      // 4 x 8B mbarriers
#define SMEM_EMPTY  32                     // 4 x 8B mbarriers
#define SMEM_EPI    64                     // 512 floats = 2048 (single buffer)
#define SMEM_SCB    2112                   // 2 x 256 floats = 2048
#define SMEM_SCA    4160                   // 2 x 128 floats = 1024
#define SMEM_A      8192                   // 1024-aligned
#define SMEM_B      (SMEM_A + STAGES * A_STAGE_BYTES)
#define SMEM_TOTAL  (SMEM_B + STAGES * B_STAGE_BYTES)   // ~205KB

// ============================================================================
// Scratch (module-load allocation, legal under _HX_ENFORCE)
// ============================================================================
__device__ __align__(1024) int8_t g_Xq[MAX_B * D_DIM];
__device__ __align__(1024) int8_t g_Wq[MAX_TS * D_DIM];
__device__ float g_sX[MAX_B];
__device__ float g_sW[MAX_TS];

// ============================================================================
// PTX helpers (base sm_80/sm_90 ISA only — target is sm_100 base, no tcgen05)
// ============================================================================
__device__ __forceinline__ uint32_t smem_u32(const void* p) {
    uint32_t a;
    asm("{ .reg .u64 t; cvta.to.shared.u64 t, %1; cvt.u32.u64 %0, t; }"
        : "=r"(a) : "l"(p));
    return a;
}

#define MBARRIER_INIT(mbar, cnt) \
    asm volatile("mbarrier.init.shared.b64 [%0], %1;" \
                 :: "r"((uint32_t)(mbar)), "r"((uint32_t)(cnt)) : "memory")
#define MBARRIER_EXPECT_TX(mbar, bytes) \
    asm volatile("mbarrier.arrive.expect_tx.shared.b64 _, [%0], %1;" \
                 :: "r"((uint32_t)(mbar)), "r"((uint32_t)(bytes)) : "memory")
#define MBARRIER_ARRIVE(mbar) \
    asm volatile("mbarrier.arrive.shared.b64 _, [%0];" \
                 :: "r"((uint32_t)(mbar)) : "memory")

#define MBARRIER_WAIT_PARITY(mbar, parity) do {                                  \
    uint32_t _m = (uint32_t)(mbar);                                              \
    uint32_t _p = (uint32_t)(parity);                                            \
    uint32_t _done;                                                              \
    asm volatile("{\n\t.reg .pred p;\n\t"                                        \
        "mbarrier.try_wait.parity.acquire.cta.shared::cta.b64 p, [%1], %2;\n\t"  \
        "selp.b32 %0, 1, 0, p;\n\t}"                                             \
        : "=r"(_done) : "r"(_m), "r"(_p) : "memory");                            \
    if (!_done) {                                                                \
        asm volatile("{\n\t.reg .pred P1;\n\t"                                   \
            "WAIT_LOOP_%=:\n\t"                                                  \
            "mbarrier.try_wait.parity.acquire.cta.shared::cta.b64 P1, [%0], %1, 0x989680;\n\t" \
            "@P1 bra.uni WAIT_DONE_%=;\n\t"                                      \
            "bra.uni WAIT_LOOP_%=;\n\t"                                          \
            "WAIT_DONE_%=:\n\t}"                                                 \
            :: "r"(_m), "r"(_p) : "memory");                                     \
    }                                                                            \
} while (0)

#define TMA_LOAD_2D(smem_addr, tmap, cx, cy, mbar) \
    asm volatile("cp.async.bulk.tensor.2d.shared::cluster.global.tile.mbarrier::complete_tx::bytes " \
                 "[%0], [%1, {%2, %3}], [%4];" \
                 :: "r"((uint32_t)(smem_addr)), "l"(tmap), \
                    "r"((int)(cx)), "r"((int)(cy)), "r"((uint32_t)(mbar)) : "memory")

// 4-byte fire-and-forget global->shared copy (sm_80 cp.async)
#define CP_ASYNC_4(smem_addr, gptr) \
    asm volatile("cp.async.ca.shared.global [%0], [%1], 4;" \
                 :: "r"((uint32_t)(smem_addr)), "l"(gptr) : "memory")
#define CP_ASYNC_COMMIT() \
    asm volatile("cp.async.commit_group;" ::: "memory")
#define CP_ASYNC_WAIT_ALL() \
    asm volatile("cp.async.wait_group 0;" ::: "memory")

#define LDSM_X4(r0, r1, r2, r3, addr) \
    asm volatile("ldmatrix.sync.aligned.m8n8.x4.shared.b16 {%0,%1,%2,%3}, [%4];" \
                 : "=r"(r0), "=r"(r1), "=r"(r2), "=r"(r3) : "r"(addr))

// int8 IMMA: byte-identical fragment layout to HMMA m16n8k16 with f16 -> 2 x s8
#define IMMA16832(c, a, b) \
    asm volatile("mma.sync.aligned.m16n8k32.row.col.s32.s8.s8.s32 " \
                 "{%0,%1,%2,%3}, {%4,%5,%6,%7}, {%8,%9}, {%0,%1,%2,%3};" \
                 : "+r"((c)[0]), "+r"((c)[1]), "+r"((c)[2]), "+r"((c)[3]) \
                 : "r"((a)[0]), "r"((a)[1]), "r"((a)[2]), "r"((a)[3]), \
                   "r"((b)[0]), "r"((b)[1]))

#define SWZ128(x) ((x) ^ (((x) >> 3) & 0x70))

// ============================================================================
// Kernel 1: fused L2-normalize + per-row symmetric int8 quantize.
// ============================================================================
__global__ void __launch_bounds__(256) normquant_kernel(
    const float* __restrict__ x, const float* __restrict__ w,
    int8_t* __restrict__ xq, int8_t* __restrict__ wq,
    float* __restrict__ sx, float* __restrict__ sw, int B) {
    int blk = blockIdx.x;
    const float* in; int8_t* outq; float* outs; int row;
    if (blk < B) { in = x; outq = xq; outs = sx; row = blk; }
    else         { in = w; outq = wq; outs = sw; row = blk - B; }

    const float4 v = reinterpret_cast<const float4*>(in)[(size_t)row * 256 + threadIdx.x];
    float ss = v.x * v.x + v.y * v.y + v.z * v.z + v.w * v.w;
    float ma = fmaxf(fmaxf(fabsf(v.x), fabsf(v.y)), fmaxf(fabsf(v.z), fabsf(v.w)));
#pragma unroll
    for (int o = 16; o > 0; o >>= 1) {
        ss += __shfl_xor_sync(0xFFFFFFFFu, ss, o);
        ma = fmaxf(ma, __shfl_xor_sync(0xFFFFFFFFu, ma, o));
    }
    __shared__ float wss[8], wma[8];
    if ((threadIdx.x & 31) == 0) { wss[threadIdx.x >> 5] = ss; wma[threadIdx.x >> 5] = ma; }
    __syncthreads();
    float tot = wss[0] + wss[1] + wss[2] + wss[3] + wss[4] + wss[5] + wss[6] + wss[7];
    float mx  = fmaxf(fmaxf(fmaxf(wma[0], wma[1]), fmaxf(wma[2], wma[3])),
                      fmaxf(fmaxf(wma[4], wma[5]), fmaxf(wma[6], wma[7])));
    float rq = 127.0f / mx;
    int q0 = __float2int_rn(v.x * rq), q1 = __float2int_rn(v.y * rq);
    int q2 = __float2int_rn(v.z * rq), q3 = __float2int_rn(v.w * rq);
    uint32_t pk = (uint32_t)(q0 & 0xFF) | ((uint32_t)(q1 & 0xFF) << 8) |
                  ((uint32_t)(q2 & 0xFF) << 16) | ((uint32_t)(q3 & 0xFF) << 24);
    reinterpret_cast<uint32_t*>(outq)[(size_t)row * 256 + threadIdx.x] = pk;
    if (threadIdx.x == 0) outs[row] = mx * rsqrtf(tot) / 127.0f;
}

// ============================================================================
// Kernel 2: PERSISTENT IMMA GEMM, 256 threads (8 warps 2Mx4N, 64x64 warp tile).
// Lagged refill (stage g-1 reloaded at top of iter g). Scale vectors staged
// into smem via cp.async at tile start (latency hidden by mainloop), so the
// epilogue + output write are pure LDS. kt loop unrolled 2x.
// ============================================================================
__global__ void __launch_bounds__(THREADS, 1) gemm_segmax_kernel(
    const __grid_constant__ CUtensorMap tma_a,
    const __grid_constant__ CUtensorMap tma_b,
    const float* __restrict__ sA, const float* __restrict__ sB,
    float* __restrict__ out, int num_tasks, int n_mtiles, int total_tiles) {
    extern __shared__ char smem[];
    uint32_t sb = smem_u32(smem);
    int tid = threadIdx.x;
    int wid = tid >> 5;
    int l   = tid & 31;
    int warp_m = wid >> 2;   // 0..1 -> rows warp_m*64
    int warp_n = wid & 3;    // 0..3 -> cols warp_n*64

    int ntile_cta = 0;
    for (int t = blockIdx.x; t < total_tiles; t += gridDim.x) ntile_cta++;
    if (ntile_cta == 0) return;
    int total_stg = ntile_cta * NK;

    if (tid == 0) {
#pragma unroll
        for (int s = 0; s < STAGES; s++) {
            MBARRIER_INIT(sb + SMEM_FULL  + s * 8, 1);
            MBARRIER_INIT(sb + SMEM_EMPTY + s * 8, NWC);
        }
    }
    __syncthreads();

    // ---- Prologue: fill all 4 stages ----
    if (tid == 0) {
        int m0p = (blockIdx.x % n_mtiles) * M_TILE;
        int n0p = (blockIdx.x / n_mtiles) * N_TILE;
#pragma unroll
        for (int gg = 0; gg < STAGES; gg++) {
            uint32_t fb = sb + SMEM_FULL + gg * 8;
            MBARRIER_EXPECT_TX(fb, STAGE_BYTES);
            TMA_LOAD_2D(sb + SMEM_A + gg * A_STAGE_BYTES, &tma_a, gg * K_TILE, m0p, fb);
            TMA_LOAD_2D(sb + SMEM_B + gg * B_STAGE_BYTES, &tma_b, gg * K_TILE, n0p, fb);
        }
    }

    // Lane-invariant byte offsets within a stage tile (row stride 128B)
    uint32_t aoff[4];
#pragma unroll
    for (int mt = 0; mt < 4; mt++)
        aoff[mt] = (uint32_t)(warp_m * 64 + mt * 16 + (l & 15)) * 128 + ((l >> 4) & 1) * 16;
    uint32_t boff[4];
#pragma unroll
    for (int jp = 0; jp < 4; jp++)
        boff[jp] = (uint32_t)(warp_n * 64 + jp * 16 + ((l & 16) >> 1) + (l & 7)) * 128
                 + ((l & 8) ? 16u : 0u);

    float* epi = reinterpret_cast<float*>(smem + SMEM_EPI);
    int g = 0;                               // global stage counter
    int ebuf = 0;                            // scale buffer selector
    for (int t = blockIdx.x; t < total_tiles; t += gridDim.x) {
        int m0 = (t % n_mtiles) * M_TILE;
        int n0 = (t / n_mtiles) * N_TILE;

        // ---- fire-and-forget scale staging (hidden by the mainloop) ----
        float* scb = reinterpret_cast<float*>(smem + SMEM_SCB) + ebuf * 256;
        float* sca = reinterpret_cast<float*>(smem + SMEM_SCA) + ebuf * 128;
        CP_ASYNC_4(sb + SMEM_SCB + ebuf * 1024 + tid * 4, &sB[n0 + tid]);
        if (tid < 128)
            CP_ASYNC_4(sb + SMEM_SCA + ebuf * 512 + tid * 4, &sA[m0 + tid]);
        CP_ASYNC_COMMIT();

        int c[4][8][4];
#pragma unroll
        for (int mt = 0; mt < 4; mt++)
#pragma unroll
            for (int j = 0; j < 8; j++)
#pragma unroll
                for (int i = 0; i < 4; i++) c[mt][j][i] = 0;

#pragma unroll 2
        for (int kt = 0; kt < NK; kt++, g++) {
            int s = g & (STAGES - 1);
            int ph = (g >> 2) & 1;
            uint32_t fb = sb + SMEM_FULL  + s * 8;
            uint32_t eb = sb + SMEM_EMPTY + s * 8;

            // ---- lagged refill: stage consumed LAST iteration (g-1) ----
            if (tid == 0 && g > 0) {
                int gp = g - 1;
                int gr = gp + STAGES;
                if (gr < total_stg) {
                    int sp  = gp & (STAGES - 1);
                    int php = (gp >> 2) & 1;
                    uint32_t ebp = sb + SMEM_EMPTY + sp * 8;
                    uint32_t fbp = sb + SMEM_FULL  + sp * 8;
                    MBARRIER_WAIT_PARITY(ebp, php);
                    int tt = gr / NK, ktt = gr % NK;
                    int tgl = blockIdx.x + tt * gridDim.x;
                    MBARRIER_EXPECT_TX(fbp, STAGE_BYTES);
                    TMA_LOAD_2D(sb + SMEM_A + sp * A_STAGE_BYTES, &tma_a,
                                ktt * K_TILE, (tgl % n_mtiles) * M_TILE, fbp);
                    TMA_LOAD_2D(sb + SMEM_B + sp * B_STAGE_BYTES, &tma_b,
                                ktt * K_TILE, (tgl / n_mtiles) * N_TILE, fbp);
                }
            }

            MBARRIER_WAIT_PARITY(fb, ph);

            uint32_t a_sb = sb + SMEM_A + s * A_STAGE_BYTES;
            uint32_t b_sb = sb + SMEM_B + s * B_STAGE_BYTES;

#pragma unroll
            for (int ks = 0; ks < 4; ks++) {          // 4 x k32 per 128B stage
                uint32_t a[4][4];
#pragma unroll
                for (int mt = 0; mt < 4; mt++) {
                    uint32_t off = aoff[mt] + ks * 32;
                    LDSM_X4(a[mt][0], a[mt][1], a[mt][2], a[mt][3], a_sb + SWZ128(off));
                }
                uint32_t b[8][2];
#pragma unroll
                for (int jp = 0; jp < 4; jp++) {
                    uint32_t off = boff[jp] + ks * 32;
                    LDSM_X4(b[2 * jp][0], b[2 * jp][1], b[2 * jp + 1][0], b[2 * jp + 1][1],
                            b_sb + SWZ128(off));
                }
#pragma unroll
                for (int mt = 0; mt < 4; mt++)
#pragma unroll
                    for (int j = 0; j < 8; j++)
                        IMMA16832(c[mt][j], a[mt], b[j]);
            }
            if (l == 0) MBARRIER_ARRIVE(eb);          // warp done with stage s
        }

        // ---- Epilogue: sB[col] scale, segmented max, sA[row] scale ----
        CP_ASYNC_WAIT_ALL();
        __syncthreads();          // scales visible; epi free (prev out-read done)

        int col0 = warp_n * 64 + 2 * (l & 3);
#pragma unroll
        for (int mt = 0; mt < 4; mt++) {
            float mlo = -1e30f, mhi = -1e30f;
#pragma unroll
            for (int j = 0; j < 8; j++) {
                float s0 = scb[col0 + j * 8];
                float s1 = scb[col0 + j * 8 + 1];
                mlo = fmaxf(mlo, fmaxf((float)c[mt][j][0] * s0, (float)c[mt][j][1] * s1));
                mhi = fmaxf(mhi, fmaxf((float)c[mt][j][2] * s0, (float)c[mt][j][3] * s1));
            }
            mlo = fmaxf(mlo, __shfl_xor_sync(0xFFFFFFFFu, mlo, 1));
            mlo = fmaxf(mlo, __shfl_xor_sync(0xFFFFFFFFu, mlo, 2));
            mhi = fmaxf(mhi, __shfl_xor_sync(0xFFFFFFFFu, mhi, 1));
            mhi = fmaxf(mhi, __shfl_xor_sync(0xFFFFFFFFu, mhi, 2));
            if ((l & 3) == 0) {
                int rlo = warp_m * 64 + mt * 16 + (l >> 2);
                epi[warp_n * 128 + rlo]     = mlo;
                epi[warp_n * 128 + rlo + 8] = mhi;
            }
        }
        __syncthreads();

        if (tid < 128) {
            float v = fmaxf(fmaxf(epi[tid], epi[128 + tid]),
                            fmaxf(epi[256 + tid], epi[384 + tid]));
            float dot = v * sca[tid];
            float sq = fmaxf(2.0f - 2.0f * dot, 1e-12f);
            out[(size_t)(m0 + tid) * num_tasks + (t / n_mtiles)] = -sqrtf(sq);
        }
        ebuf ^= 1;
    }
}

// ============================================================================
// Host side
// ============================================================================
typedef CUresult (*EncodeFn)(CUtensorMap*, CUtensorMapDataType, cuuint32_t, void*,
                             const cuuint64_t*, const cuuint64_t*, const cuuint32_t*,
                             const cuuint32_t*, CUtensorMapInterleave, CUtensorMapSwizzle,
                             CUtensorMapL2promotion, CUtensorMapFloatOOBfill);

static void encode_2d(EncodeFn enc, CUtensorMap* tm, void* ptr,
                      uint64_t rows, uint32_t box_rows) {
    cuuint64_t dims[2]    = {D_DIM, rows};
    cuuint64_t strides[1] = {D_DIM};              // int8: 1024 bytes per row
    cuuint32_t box[2]     = {K_TILE, box_rows};   // 128 int8 = 128B = SW128 span
    cuuint32_t es[2]      = {1, 1};
    enc(tm, CU_TENSOR_MAP_DATA_TYPE_UINT8, 2, ptr, dims, strides, box, es,
        CU_TENSOR_MAP_INTERLEAVE_NONE, CU_TENSOR_MAP_SWIZZLE_128B,
        CU_TENSOR_MAP_L2_PROMOTION_L2_128B, CU_TENSOR_MAP_FLOAT_OOB_FILL_NONE);
}

extern "C" void kernel_launch(void* const* d_in, const int* in_sizes, int n_in,
                              void* d_out, int out_size) {
    const float* x = (const float*)d_in[0];
    const float* w = (const float*)d_in[1];
    const int B  = in_sizes[0] / D_DIM;   // 8192
    const int TS = in_sizes[1] / D_DIM;   // 5120
    const int T  = TS / 256;              // 20
    float* out = (float*)d_out;

    int8_t *dXq = nullptr, *dWq = nullptr;
    float *dsX = nullptr, *dsW = nullptr;
    cudaGetSymbolAddress((void**)&dXq, g_Xq);
    cudaGetSymbolAddress((void**)&dWq, g_Wq);
    cudaGetSymbolAddress((void**)&dsX, g_sX);
    cudaGetSymbolAddress((void**)&dsW, g_sW);

    normquant_kernel<<<B + TS, 256>>>(x, w, dXq, dWq, dsX, dsW, B);

    void* fn = nullptr;
    cudaDriverEntryPointQueryResult qr;
    cudaGetDriverEntryPoint("cuTensorMapEncodeTiled", &fn, cudaEnableDefault, &qr);
    EncodeFn enc = (EncodeFn)fn;

    CUtensorMap tma_a, tma_b;
    encode_2d(enc, &tma_a, dXq, (uint64_t)B,  M_TILE);
    encode_2d(enc, &tma_b, dWq, (uint64_t)TS, N_TILE);

    int nsm = 148;
    cudaDeviceGetAttribute(&nsm, cudaDevAttrMultiProcessorCount, 0);

    int n_mtiles = B / M_TILE;            // 64
    int total_tiles = n_mtiles * T;       // 1280

    cudaFuncSetAttribute(gemm_segmax_kernel,
                         cudaFuncAttributeMaxDynamicSharedMemorySize, SMEM_TOTAL);
    gemm_segmax_kernel<<<nsm, THREADS, SMEM_TOTAL>>>(
        tma_a, tma_b, dsX, dsW, out, T, n_mtiles, total_tiles);
}

// round 12
// speedup vs baseline: 1.1379x; 1.0784x over previous
#include <cuda_runtime.h>
#include <cuda.h>
#include <cuda_bf16.h>
#include <cstdint>

// ============================================================================
// Problem constants (fixed by setup_inputs: B=8192, D=1024, T=20, S=256)
// ============================================================================
#define D_DIM   1024
#define MAX_B   8192
#define MAX_TS  5120

#define M_TILE  128
#define N_TILE  256               // == BUFFER_SIZE -> segmented min is CTA-local
#define K_TILE  128               // int8: 128 elems = 128B = one SW128 atom row
#define NK      (D_DIM / K_TILE)  // 8 K-stages per tile
#define STAGES  4
#define NWC     8                 // 8 warps: 2(M) x 4(N), warp tile 64x64
#define THREADS (NWC * 32)        // 256

#define A_STAGE_BYTES (M_TILE * 128)                    // 16384
#define B_STAGE_BYTES (N_TILE * 128)                    // 32768
#define STAGE_BYTES   (A_STAGE_BYTES + B_STAGE_BYTES)   // 49152

#define SMEM_FULL   0                      // 4 x 8B mbarriers
#define SMEM_EMPTY  32                     // 4 x 8B mbarriers
#define SMEM_EPI    64                     // 2 buffers x 512 floats = 4096
#define SMEM_A      8192                   // 1024-aligned
#define SMEM_B      (SMEM_A + STAGES * A_STAGE_BYTES)
#define SMEM_TOTAL  (SMEM_B + STAGES * B_STAGE_BYTES)

// ============================================================================
// Scratch (module-load allocation, legal under _HX_ENFORCE)
// ============================================================================
__device__ __align__(1024) int8_t g_Xq[MAX_B * D_DIM];
__device__ __align__(1024) int8_t g_Wq[MAX_TS * D_DIM];
__device__ float g_sX[MAX_B];
__device__ float g_sW[MAX_TS];

// ============================================================================
// PTX helpers (base sm_80/sm_90 ISA only — target is sm_100 base, no tcgen05)
// ============================================================================
__device__ __forceinline__ uint32_t smem_u32(const void* p) {
    uint32_t a;
    asm("{ .reg .u64 t; cvta.to.shared.u64 t, %1; cvt.u32.u64 %0, t; }"
        : "=r"(a) : "l"(p));
    return a;
}

#define MBARRIER_INIT(mbar, cnt) \
    asm volatile("mbarrier.init.shared.b64 [%0], %1;" \
                 :: "r"((uint32_t)(mbar)), "r"((uint32_t)(cnt)) : "memory")
#define MBARRIER_EXPECT_TX(mbar, bytes) \
    asm volatile("mbarrier.arrive.expect_tx.shared.b64 _, [%0], %1;" \
                 :: "r"((uint32_t)(mbar)), "r"((uint32_t)(bytes)) : "memory")
#define MBARRIER_ARRIVE(mbar) \
    asm volatile("mbarrier.arrive.shared.b64 _, [%0];" \
                 :: "r"((uint32_t)(mbar)) : "memory")

#define MBARRIER_WAIT_PARITY(mbar, parity) do {                                  \
    uint32_t _m = (uint32_t)(mbar);                                              \
    uint32_t _p = (uint32_t)(parity);                                            \
    uint32_t _done;                                                              \
    asm volatile("{\n\t.reg .pred p;\n\t"                                        \
        "mbarrier.try_wait.parity.acquire.cta.shared::cta.b64 p, [%1], %2;\n\t"  \
        "selp.b32 %0, 1, 0, p;\n\t}"                                             \
        : "=r"(_done) : "r"(_m), "r"(_p) : "memory");                            \
    if (!_done) {                                                                \
        asm volatile("{\n\t.reg .pred P1;\n\t"                                   \
            "WAIT_LOOP_%=:\n\t"                                                  \
            "mbarrier.try_wait.parity.acquire.cta.shared::cta.b64 P1, [%0], %1, 0x989680;\n\t" \
            "@P1 bra.uni WAIT_DONE_%=;\n\t"                                      \
            "bra.uni WAIT_LOOP_%=;\n\t"                                          \
            "WAIT_DONE_%=:\n\t}"                                                 \
            :: "r"(_m), "r"(_p) : "memory");                                     \
    }                                                                            \
} while (0)

#define TMA_LOAD_2D(smem_addr, tmap, cx, cy, mbar) \
    asm volatile("cp.async.bulk.tensor.2d.shared::cluster.global.tile.mbarrier::complete_tx::bytes " \
                 "[%0], [%1, {%2, %3}], [%4];" \
                 :: "r"((uint32_t)(smem_addr)), "l"(tmap), \
                    "r"((int)(cx)), "r"((int)(cy)), "r"((uint32_t)(mbar)) : "memory")

#define LDSM_X4(r0, r1, r2, r3, addr) \
    asm volatile("ldmatrix.sync.aligned.m8n8.x4.shared.b16 {%0,%1,%2,%3}, [%4];" \
                 : "=r"(r0), "=r"(r1), "=r"(r2), "=r"(r3) : "r"(addr))

// int8 IMMA: byte-identical fragment layout to HMMA m16n8k16 with f16 -> 2 x s8
#define IMMA16832(c, a, b) \
    asm volatile("mma.sync.aligned.m16n8k32.row.col.s32.s8.s8.s32 " \
                 "{%0,%1,%2,%3}, {%4,%5,%6,%7}, {%8,%9}, {%0,%1,%2,%3};" \
                 : "+r"((c)[0]), "+r"((c)[1]), "+r"((c)[2]), "+r"((c)[3]) \
                 : "r"((a)[0]), "r"((a)[1]), "r"((a)[2]), "r"((a)[3]), \
                   "r"((b)[0]), "r"((b)[1]))

#define SWZ128(x) ((x) ^ (((x) >> 3) & 0x70))

// ============================================================================
// Kernel 1: fused L2-normalize + per-row symmetric int8 quantize.
// 4 rows per 256-thread block; 64 threads/row; 4 float4 loads/thread (MLP=4).
// ============================================================================
__global__ void __launch_bounds__(256) normquant_kernel(
    const float* __restrict__ x, const float* __restrict__ w,
    int8_t* __restrict__ xq, int8_t* __restrict__ wq,
    float* __restrict__ sx, float* __restrict__ sw, int B) {
    int rid  = blockIdx.x * 4 + (threadIdx.x >> 6);   // global row id
    int lane = threadIdx.x & 63;                      // 0..63 within row group
    bool isX = rid < B;
    const float* in = isX ? x : w;
    int row = isX ? rid : rid - B;
    int8_t* outq = isX ? xq : wq;
    float* outs  = isX ? sx : sw;

    // 4 independent float4 loads (256 float4 per row / 64 threads)
    const float4* src = reinterpret_cast<const float4*>(in) + (size_t)row * 256;
    float4 v[4];
#pragma unroll
    for (int j = 0; j < 4; j++) v[j] = src[lane + j * 64];

    float ss = 0.0f, ma = 0.0f;
#pragma unroll
    for (int j = 0; j < 4; j++) {
        ss += v[j].x * v[j].x + v[j].y * v[j].y + v[j].z * v[j].z + v[j].w * v[j].w;
        ma = fmaxf(ma, fmaxf(fmaxf(fabsf(v[j].x), fabsf(v[j].y)),
                             fmaxf(fabsf(v[j].z), fabsf(v[j].w))));
    }
#pragma unroll
    for (int o = 16; o > 0; o >>= 1) {
        ss += __shfl_xor_sync(0xFFFFFFFFu, ss, o);
        ma = fmaxf(ma, __shfl_xor_sync(0xFFFFFFFFu, ma, o));
    }
    // combine the 2 warps of each row group via smem
    __shared__ float wss[4][2], wma[4][2];
    int rgrp = threadIdx.x >> 6;         // row slot 0..3
    int wslot = (threadIdx.x >> 5) & 1;  // warp within row group
    if ((threadIdx.x & 31) == 0) { wss[rgrp][wslot] = ss; wma[rgrp][wslot] = ma; }
    __syncthreads();
    float tot = wss[rgrp][0] + wss[rgrp][1];
    float mx  = fmaxf(wma[rgrp][0], wma[rgrp][1]);

    float rq = 127.0f / mx;
    uint32_t* dst = reinterpret_cast<uint32_t*>(outq) + (size_t)row * 256;
#pragma unroll
    for (int j = 0; j < 4; j++) {
        int q0 = __float2int_rn(v[j].x * rq), q1 = __float2int_rn(v[j].y * rq);
        int q2 = __float2int_rn(v[j].z * rq), q3 = __float2int_rn(v[j].w * rq);
        dst[lane + j * 64] = (uint32_t)(q0 & 0xFF) | ((uint32_t)(q1 & 0xFF) << 8) |
                             ((uint32_t)(q2 & 0xFF) << 16) | ((uint32_t)(q3 & 0xFF) << 24);
    }
    if (lane == 0) outs[row] = mx * rsqrtf(tot) / 127.0f;
}

// ============================================================================
// Kernel 2: PERSISTENT IMMA GEMM (round-9 winner, unchanged).
// 256 threads (8 warps 2Mx4N, 64x64 warp tile). Lagged refill: at the top of
// iteration g, tid 0 waits on the empty barrier of stage g-1 (consumed last
// iteration -> wait almost always satisfied) and loads stage g-1+4.
// Epilogue smem double-buffered -> single __syncthreads per tile.
// ============================================================================
__global__ void __launch_bounds__(THREADS, 1) gemm_segmax_kernel(
    const __grid_constant__ CUtensorMap tma_a,
    const __grid_constant__ CUtensorMap tma_b,
    const float* __restrict__ sA, const float* __restrict__ sB,
    float* __restrict__ out, int num_tasks, int n_mtiles, int total_tiles) {
    extern __shared__ char smem[];
    uint32_t sb = smem_u32(smem);
    int tid = threadIdx.x;
    int wid = tid >> 5;
    int l   = tid & 31;
    int warp_m = wid >> 2;   // 0..1 -> rows warp_m*64
    int warp_n = wid & 3;    // 0..3 -> cols warp_n*64

    int ntile_cta = 0;
    for (int t = blockIdx.x; t < total_tiles; t += gridDim.x) ntile_cta++;
    if (ntile_cta == 0) return;
    int total_stg = ntile_cta * NK;

    if (tid == 0) {
#pragma unroll
        for (int s = 0; s < STAGES; s++) {
            MBARRIER_INIT(sb + SMEM_FULL  + s * 8, 1);
            MBARRIER_INIT(sb + SMEM_EMPTY + s * 8, NWC);
        }
    }
    __syncthreads();

    // ---- Prologue: fill all 4 stages ----
    if (tid == 0) {
        int m0p = (blockIdx.x % n_mtiles) * M_TILE;
        int n0p = (blockIdx.x / n_mtiles) * N_TILE;
#pragma unroll
        for (int gg = 0; gg < STAGES; gg++) {
            uint32_t fb = sb + SMEM_FULL + gg * 8;
            MBARRIER_EXPECT_TX(fb, STAGE_BYTES);
            TMA_LOAD_2D(sb + SMEM_A + gg * A_STAGE_BYTES, &tma_a, gg * K_TILE, m0p, fb);
            TMA_LOAD_2D(sb + SMEM_B + gg * B_STAGE_BYTES, &tma_b, gg * K_TILE, n0p, fb);
        }
    }

    // Lane-invariant byte offsets within a stage tile (row stride 128B)
    uint32_t aoff[4];
#pragma unroll
    for (int mt = 0; mt < 4; mt++)
        aoff[mt] = (uint32_t)(warp_m * 64 + mt * 16 + (l & 15)) * 128 + ((l >> 4) & 1) * 16;
    uint32_t boff[4];
#pragma unroll
    for (int jp = 0; jp < 4; jp++)
        boff[jp] = (uint32_t)(warp_n * 64 + jp * 16 + ((l & 16) >> 1) + (l & 7)) * 128
                 + ((l & 8) ? 16u : 0u);

    int g = 0;                               // global stage counter
    int ebuf = 0;                            // epilogue buffer selector
    for (int t = blockIdx.x; t < total_tiles; t += gridDim.x) {
        int m0 = (t % n_mtiles) * M_TILE;
        int n0 = (t / n_mtiles) * N_TILE;

        int c[4][8][4];
#pragma unroll
        for (int mt = 0; mt < 4; mt++)
#pragma unroll
            for (int j = 0; j < 8; j++)
#pragma unroll
                for (int i = 0; i < 4; i++) c[mt][j][i] = 0;

#pragma unroll 1
        for (int kt = 0; kt < NK; kt++, g++) {
            int s = g & (STAGES - 1);
            int ph = (g >> 2) & 1;
            uint32_t fb = sb + SMEM_FULL  + s * 8;
            uint32_t eb = sb + SMEM_EMPTY + s * 8;

            // ---- lagged refill: stage consumed LAST iteration (g-1) ----
            if (tid == 0 && g > 0) {
                int gp = g - 1;
                int gr = gp + STAGES;
                if (gr < total_stg) {
                    int sp  = gp & (STAGES - 1);
                    int php = (gp >> 2) & 1;
                    uint32_t ebp = sb + SMEM_EMPTY + sp * 8;
                    uint32_t fbp = sb + SMEM_FULL  + sp * 8;
                    MBARRIER_WAIT_PARITY(ebp, php);
                    int tt = gr / NK, ktt = gr % NK;
                    int tgl = blockIdx.x + tt * gridDim.x;
                    MBARRIER_EXPECT_TX(fbp, STAGE_BYTES);
                    TMA_LOAD_2D(sb + SMEM_A + sp * A_STAGE_BYTES, &tma_a,
                                ktt * K_TILE, (tgl % n_mtiles) * M_TILE, fbp);
                    TMA_LOAD_2D(sb + SMEM_B + sp * B_STAGE_BYTES, &tma_b,
                                ktt * K_TILE, (tgl / n_mtiles) * N_TILE, fbp);
                }
            }

            MBARRIER_WAIT_PARITY(fb, ph);

            uint32_t a_sb = sb + SMEM_A + s * A_STAGE_BYTES;
            uint32_t b_sb = sb + SMEM_B + s * B_STAGE_BYTES;

#pragma unroll
            for (int ks = 0; ks < 4; ks++) {          // 4 x k32 per 128B stage
                uint32_t a[4][4];
#pragma unroll
                for (int mt = 0; mt < 4; mt++) {
                    uint32_t off = aoff[mt] + ks * 32;
                    LDSM_X4(a[mt][0], a[mt][1], a[mt][2], a[mt][3], a_sb + SWZ128(off));
                }
                uint32_t b[8][2];
#pragma unroll
                for (int jp = 0; jp < 4; jp++) {
                    uint32_t off = boff[jp] + ks * 32;
                    LDSM_X4(b[2 * jp][0], b[2 * jp][1], b[2 * jp + 1][0], b[2 * jp + 1][1],
                            b_sb + SWZ128(off));
                }
#pragma unroll
                for (int mt = 0; mt < 4; mt++)
#pragma unroll
                    for (int j = 0; j < 8; j++)
                        IMMA16832(c[mt][j], a[mt], b[j]);
            }
            if (l == 0) MBARRIER_ARRIVE(eb);          // warp done with stage s
        }

        // ---- Epilogue: sB[col] scale, segmented max, sA[row] scale ----
        float* epi = reinterpret_cast<float*>(smem + SMEM_EPI) + ebuf * 512;
        int col0 = warp_n * 64 + 2 * (l & 3);
#pragma unroll
        for (int mt = 0; mt < 4; mt++) {
            float mlo = -1e30f, mhi = -1e30f;
#pragma unroll
            for (int j = 0; j < 8; j++) {
                float s0 = __ldg(&sB[n0 + col0 + j * 8]);
                float s1 = __ldg(&sB[n0 + col0 + j * 8 + 1]);
                mlo = fmaxf(mlo, fmaxf((float)c[mt][j][0] * s0, (float)c[mt][j][1] * s1));
                mhi = fmaxf(mhi, fmaxf((float)c[mt][j][2] * s0, (float)c[mt][j][3] * s1));
            }
            mlo = fmaxf(mlo, __shfl_xor_sync(0xFFFFFFFFu, mlo, 1));
            mlo = fmaxf(mlo, __shfl_xor_sync(0xFFFFFFFFu, mlo, 2));
            mhi = fmaxf(mhi, __shfl_xor_sync(0xFFFFFFFFu, mhi, 1));
            mhi = fmaxf(mhi, __shfl_xor_sync(0xFFFFFFFFu, mhi, 2));
            if ((l & 3) == 0) {
                int rlo = warp_m * 64 + mt * 16 + (l >> 2);
                epi[warp_n * 128 + rlo]     = mlo;
                epi[warp_n * 128 + rlo + 8] = mhi;
            }
        }
        __syncthreads();    // single barrier per tile (epi is double-buffered)

        if (tid < 128) {
            float v = fmaxf(fmaxf(epi[tid], epi[128 + tid]),
                            fmaxf(epi[256 + tid], epi[384 + tid]));
            float dot = v * __ldg(&sA[m0 + tid]);
            float sq = fmaxf(2.0f - 2.0f * dot, 1e-12f);
            out[(size_t)(m0 + tid) * num_tasks + (t / n_mtiles)] = -sqrtf(sq);
        }
        ebuf ^= 1;
    }
}

// ============================================================================
// Host side
// ============================================================================
typedef CUresult (*EncodeFn)(CUtensorMap*, CUtensorMapDataType, cuuint32_t, void*,
                             const cuuint64_t*, const cuuint64_t*, const cuuint32_t*,
                             const cuuint32_t*, CUtensorMapInterleave, CUtensorMapSwizzle,
                             CUtensorMapL2promotion, CUtensorMapFloatOOBfill);

static void encode_2d(EncodeFn enc, CUtensorMap* tm, void* ptr,
                      uint64_t rows, uint32_t box_rows) {
    cuuint64_t dims[2]    = {D_DIM, rows};
    cuuint64_t strides[1] = {D_DIM};              // int8: 1024 bytes per row
    cuuint32_t box[2]     = {K_TILE, box_rows};   // 128 int8 = 128B = SW128 span
    cuuint32_t es[2]      = {1, 1};
    enc(tm, CU_TENSOR_MAP_DATA_TYPE_UINT8, 2, ptr, dims, strides, box, es,
        CU_TENSOR_MAP_INTERLEAVE_NONE, CU_TENSOR_MAP_SWIZZLE_128B,
        CU_TENSOR_MAP_L2_PROMOTION_L2_128B, CU_TENSOR_MAP_FLOAT_OOB_FILL_NONE);
}

extern "C" void kernel_launch(void* const* d_in, const int* in_sizes, int n_in,
                              void* d_out, int out_size) {
    const float* x = (const float*)d_in[0];
    const float* w = (const float*)d_in[1];
    const int B  = in_sizes[0] / D_DIM;   // 8192
    const int TS = in_sizes[1] / D_DIM;   // 5120
    const int T  = TS / 256;              // 20
    float* out = (float*)d_out;

    int8_t *dXq = nullptr, *dWq = nullptr;
    float *dsX = nullptr, *dsW = nullptr;
    cudaGetSymbolAddress((void**)&dXq, g_Xq);
    cudaGetSymbolAddress((void**)&dWq, g_Wq);
    cudaGetSymbolAddress((void**)&dsX, g_sX);
    cudaGetSymbolAddress((void**)&dsW, g_sW);

    normquant_kernel<<<(B + TS) / 4, 256>>>(x, w, dXq, dWq, dsX, dsW, B);

    void* fn = nullptr;
    cudaDriverEntryPointQueryResult qr;
    cudaGetDriverEntryPoint("cuTensorMapEncodeTiled", &fn, cudaEnableDefault, &qr);
    EncodeFn enc = (EncodeFn)fn;

    CUtensorMap tma_a, tma_b;
    encode_2d(enc, &tma_a, dXq, (uint64_t)B,  M_TILE);
    encode_2d(enc, &tma_b, dWq, (uint64_t)TS, N_TILE);

    int nsm = 148;
    cudaDeviceGetAttribute(&nsm, cudaDevAttrMultiProcessorCount, 0);

    int n_mtiles = B / M_TILE;            // 64
    int total_tiles = n_mtiles * T;       // 1280

    cudaFuncSetAttribute(gemm_segmax_kernel,
                         cudaFuncAttributeMaxDynamicSharedMemorySize, SMEM_TOTAL);
    gemm_segmax_kernel<<<nsm, THREADS, SMEM_TOTAL>>>(
        tma_a, tma_b, dsX, dsW, out, T, n_mtiles, total_tiles);
}